// round 6
// baseline (speedup 1.0000x reference)
#include <cuda_runtime.h>
#include <cuda_fp16.h>

#define H        64
#define NPIX     65536
#define LBATCH   8
#define NSPLIT   74                      // 8*74 = 592 CTAs = 148 SMs * 4 CTAs (1 wave)
#define NCTA     (LBATCH * NSPLIT)
#define NCHUNKS  1024                    // 64-pixel chunks per image

// scratch: per-CTA 3 GEMM tiles: [cta][gemm][64*64]
__device__ float g_part[(size_t)NCTA * 3 * H * H];
// per-reduce-block partial totals: [lc][16 blocks]
__device__ float g_bsum[LBATCH * 3 * 16];

__device__ __forceinline__ unsigned pk(float lo, float hi) {  // f32x2 -> f16x2
    unsigned r; asm("cvt.rn.f16x2.f32 %0, %2, %1;" : "=r"(r) : "f"(lo), "f"(hi));
    return r;
}
__device__ __forceinline__ unsigned hm2(unsigned a, unsigned b) {
    unsigned r; asm("mul.rn.f16x2 %0, %1, %2;" : "=r"(r) : "r"(a), "r"(b));
    return r;
}
__device__ __forceinline__ float lg2a(float x) {
    float r; asm("lg2.approx.f32 %0, %1;" : "=f"(r) : "f"(x));
    return r;
}
__device__ __forceinline__ float sqrta(float x) {
    float r; asm("sqrt.approx.f32 %0, %1;" : "=f"(r) : "f"(x));
    return r;
}
// two kernel values (pixels u0,u1 at same bin), sqrt-weight folded:
//   sw2 * 1/(1 + u^2), f16x2 (1 MUFU per 2 values). u stays f32 for precision.
__device__ __forceinline__ unsigned kv(float u0, float u1, unsigned sw2) {
    unsigned u = pk(u0, u1);
    unsigned t;
    asm("fma.rn.f16x2 %0, %1, %1, %2;" : "=r"(t) : "r"(u), "r"(0x3C003C00u));
    __half2 th = *(__half2*)&t;
    __half2 rh = h2rcp(th);
    return hm2(*(unsigned*)&rh, sw2);
}
__device__ __forceinline__ void mma16816(float* c, const unsigned* a, unsigned b0, unsigned b1) {
    asm volatile(
        "mma.sync.aligned.m16n8k16.row.col.f32.f16.f16.f32 "
        "{%0,%1,%2,%3}, {%4,%5,%6,%7}, {%8,%9}, {%0,%1,%2,%3};"
        : "+f"(c[0]), "+f"(c[1]), "+f"(c[2]), "+f"(c[3])
        : "r"(a[0]), "r"(a[1]), "r"(a[2]), "r"(a[3]), "r"(b0), "r"(b1));
}
__device__ __forceinline__ float shf(float v, int src) {
    return __shfl_sync(0xffffffffu, v, src);
}

// 6 warps per CTA. Warp w: g = w%3 (vector/GEMM id), h = w/3 (pixel half).
// Fully decoupled until one sync: each warp loads all 3 channels of ITS 32
// pixels, computes d_g + sw locally, shuffles into fragment order, produces
// vec g's fragment image for K-steps {2h,2h+1} into the current buffer.
// One __syncthreads, then consumes GEMM g (A=img[g>>1], B=img[g?2:1]),
// N-columns [32h, 32h+32). Buffers alternate per chunk (WAR-safe).
__global__ __launch_bounds__(192, 4) void hist_main(const float* __restrict__ x) {
    __shared__ uint4 img[2][3 * 4 * 4 * 32];   // [buf][vec][st][mtile][lane], 48 KB

    const int tid = threadIdx.x;
    const int w = tid >> 5;
    const int L = tid & 31;
    const int g = w % 3, h = w / 3;
    const int bx = blockIdx.x;
    const int l = bx / NSPLIT, split = bx % NSPLIT;
    const int cbeg = (split * NCHUNKS) / NSPLIT;
    const int cend = ((split + 1) * NCHUNKS) / NSPLIT;
    const float* __restrict__ xp = x + (size_t)l * 3 * NPIX + 32 * h + L;

    float acc[4][4][4];
#pragma unroll
    for (int m = 0; m < 4; m++)
#pragma unroll
        for (int j = 0; j < 4; j++)
#pragma unroll
            for (int k = 0; k < 4; k++) acc[m][j][k] = 0.0f;

    const float DLT = (6.0f / 63.0f) * 50.0f;             // scaled bin spacing
    const float ro_base = -150.0f + (float)(L >> 2) * DLT;
    const float ro_step = 8.0f * DLT;
    const int q = L & 3;
    const int aimg = g >> 1;                  // A-operand image per GEMM
    const int bimg = (g == 0) ? 1 : 2;        // B-operand image per GEMM
    const float SC = 34.65735903f;            // ln(2)/sigma

    // prefetch first chunk (all 3 channels of this warp's 32 pixels)
    float pi0 = xp[(size_t)cbeg * 64];
    float pi1 = xp[(size_t)cbeg * 64 + NPIX];
    float pi2 = xp[(size_t)cbeg * 64 + 2 * NPIX];

    int buf = 0;
#pragma unroll 1
    for (int ch = cbeg; ch < cend; ch++) {
        float i0 = fminf(fmaxf(pi0, 0.0f), 1.0f);
        float i1 = fminf(fmaxf(pi1, 0.0f), 1.0f);
        float i2 = fminf(fmaxf(pi2, 0.0f), 1.0f);
        if (ch + 1 < cend) {                  // prefetch next chunk early
            pi0 = xp[(size_t)(ch + 1) * 64];
            pi1 = xp[(size_t)(ch + 1) * 64 + NPIX];
            pi2 = xp[(size_t)(ch + 1) * 64 + 2 * NPIX];
        }
        float l0 = lg2a(i0 + 1e-6f);
        float l1 = lg2a(i1 + 1e-6f);
        float l2 = lg2a(i2 + 1e-6f);
        float d = (g == 0) ? (l0 - l1) : (g == 1) ? (l0 - l2) : (l1 - l2);
        d *= SC;
        float s = fmaf(i0, i0, fmaf(i1, i1, fmaf(i2, i2, 1e-6f)));
        float sw = sqrta(sqrta(s));           // sqrt(Iy)

        // produce vec g's fragment image for K-steps 2h, 2h+1
        uint4* ib = img[buf];
#pragma unroll
        for (int si = 0; si < 2; si++) {
            const int st = 2 * h + si;
            const int b0 = 16 * si + 2 * q;
            float dA = shf(d, b0),     dB = shf(d, b0 + 1);
            float dC = shf(d, b0 + 8), dD = shf(d, b0 + 9);
            unsigned s0 = pk(shf(sw, b0),     shf(sw, b0 + 1));
            unsigned s1 = pk(shf(sw, b0 + 8), shf(sw, b0 + 9));
#pragma unroll
            for (int m = 0; m < 4; m++) {
                const float o0 = fmaf((float)(2 * m), ro_step, ro_base);
                const float o1 = o0 + ro_step;
                uint4 v;
                v.x = kv(dA - o0, dB - o0, s0);
                v.y = kv(dA - o1, dB - o1, s0);
                v.z = kv(dC - o0, dD - o0, s1);
                v.w = kv(dC - o1, dD - o1, s1);
                ib[((g * 4 + st) * 4 + m) * 32 + L] = v;
            }
        }
        __syncthreads();   // the ONLY barrier per chunk

        // consume — GEMM g, N-half h: 4 K-steps x 16 MMAs
#pragma unroll
        for (int st = 0; st < 4; st++) {
            uint4 A0 = ib[((aimg * 4 + st) * 4 + 0) * 32 + L];
            uint4 A1 = ib[((aimg * 4 + st) * 4 + 1) * 32 + L];
            uint4 A2 = ib[((aimg * 4 + st) * 4 + 2) * 32 + L];
            uint4 A3 = ib[((aimg * 4 + st) * 4 + 3) * 32 + L];
            uint4 W0 = ib[((bimg * 4 + st) * 4 + 2 * h) * 32 + L];
            uint4 W1 = ib[((bimg * 4 + st) * 4 + 2 * h + 1) * 32 + L];
            mma16816(acc[0][0], (const unsigned*)&A0, W0.x, W0.z);
            mma16816(acc[1][0], (const unsigned*)&A1, W0.x, W0.z);
            mma16816(acc[2][0], (const unsigned*)&A2, W0.x, W0.z);
            mma16816(acc[3][0], (const unsigned*)&A3, W0.x, W0.z);
            mma16816(acc[0][1], (const unsigned*)&A0, W0.y, W0.w);
            mma16816(acc[1][1], (const unsigned*)&A1, W0.y, W0.w);
            mma16816(acc[2][1], (const unsigned*)&A2, W0.y, W0.w);
            mma16816(acc[3][1], (const unsigned*)&A3, W0.y, W0.w);
            mma16816(acc[0][2], (const unsigned*)&A0, W1.x, W1.z);
            mma16816(acc[1][2], (const unsigned*)&A1, W1.x, W1.z);
            mma16816(acc[2][2], (const unsigned*)&A2, W1.x, W1.z);
            mma16816(acc[3][2], (const unsigned*)&A3, W1.x, W1.z);
            mma16816(acc[0][3], (const unsigned*)&A0, W1.y, W1.w);
            mma16816(acc[1][3], (const unsigned*)&A1, W1.y, W1.w);
            mma16816(acc[2][3], (const unsigned*)&A2, W1.y, W1.w);
            mma16816(acc[3][3], (const unsigned*)&A3, W1.y, W1.w);
        }
        buf ^= 1;
    }

    // store this warp's GEMM half-tile (non-atomic, private slot)
    float* dst = g_part + ((size_t)bx * 3 + g) * (H * H);
    const int r = L >> 2;
    const int qq = (L & 3) * 2;
#pragma unroll
    for (int m = 0; m < 4; m++)
#pragma unroll
        for (int jl = 0; jl < 4; jl++) {
            const int row0 = m * 16 + r;
            const int col = (4 * h + jl) * 8 + qq;
            *(float2*)(dst + row0 * H + col)       = make_float2(acc[m][jl][0], acc[m][jl][1]);
            *(float2*)(dst + (row0 + 8) * H + col) = make_float2(acc[m][jl][2], acc[m][jl][3]);
        }
}

// grid (16, 24), 256 threads. Sums NSPLIT splits with the channel reversal
// mapping, writes out and a per-block partial total (no atomics, no zeroing).
__global__ void hist_reduce(float* __restrict__ out) {
    const int lc = blockIdx.y;
    const int c = lc % 3, lidx = lc / 3;
    const int e = blockIdx.x * 256 + threadIdx.x;  // 0..4095
    const int u = e >> 6, v = e & 63;
    int se;
    if (c == 0)      se = e;                        // identity
    else if (c == 1) se = ((63 - u) << 6) | v;      // row reversal
    else             se = 4095 - e;                 // row+col reversal
    const float* __restrict__ src =
        g_part + ((size_t)(lidx * NSPLIT) * 3 + c) * (H * H) + se;
    float s = 0.0f;
#pragma unroll 2
    for (int sp = 0; sp < NSPLIT; sp++) s += src[(size_t)sp * 3 * (H * H)];
    out[lc * (H * H) + e] = s;

    __shared__ float red[256];
    red[threadIdx.x] = s;
    __syncthreads();
#pragma unroll
    for (int st = 128; st > 0; st >>= 1) {
        if (threadIdx.x < st) red[threadIdx.x] += red[threadIdx.x + st];
        __syncthreads();
    }
    if (threadIdx.x == 0)
        g_bsum[lc * 16 + blockIdx.x] = red[0];
}

// grid 384, 256 threads. Each block covers 256 contiguous outputs (same l).
__global__ void hist_norm(float* __restrict__ out) {
    __shared__ float red[48];
    const int l = blockIdx.x / 48;                  // 12288 per l / 256 = 48 blocks
    if (threadIdx.x < 48) red[threadIdx.x] = g_bsum[l * 48 + threadIdx.x];
    __syncthreads();
    float tot = 1e-6f;
#pragma unroll
    for (int k = 0; k < 48; k++) tot += red[k];
    const int idx = blockIdx.x * 256 + threadIdx.x;
    out[idx] = out[idx] / tot;
}

extern "C" void kernel_launch(void* const* d_in, const int* in_sizes, int n_in,
                              void* d_out, int out_size) {
    const float* x = (const float*)d_in[0];
    float* out = (float*)d_out;
    (void)in_sizes; (void)n_in; (void)out_size;

    hist_main<<<NCTA, 192>>>(x);
    hist_reduce<<<dim3(16, 24), 256>>>(out);
    hist_norm<<<384, 256>>>(out);
}

// round 7
// speedup vs baseline: 1.4825x; 1.4825x over previous
#include <cuda_runtime.h>
#include <cuda_fp16.h>

#define H        64
#define NPIX     65536
#define LBATCH   8
#define NSPLIT   55                      // 8*55 = 440 CTAs ~ 148 SMs * 3 CTAs (1 wave)
#define NCTA     (LBATCH * NSPLIT)
#define NCHUNKS  1024                    // 64-pixel chunks per image

// scratch: per-CTA 3 GEMM tiles: [cta][gemm][64*64]
__device__ float g_part[(size_t)NCTA * 3 * H * H];
// per-reduce-block partial totals: [lc][16 blocks]
__device__ float g_bsum[LBATCH * 3 * 16];

__device__ __forceinline__ unsigned pk(float lo, float hi) {  // f32x2 -> f16x2
    unsigned r; asm("cvt.rn.f16x2.f32 %0, %2, %1;" : "=r"(r) : "f"(lo), "f"(hi));
    return r;
}
__device__ __forceinline__ unsigned hm2(unsigned a, unsigned b) {
    unsigned r; asm("mul.rn.f16x2 %0, %1, %2;" : "=r"(r) : "r"(a), "r"(b));
    return r;
}
__device__ __forceinline__ float lg2a(float x) {
    float r; asm("lg2.approx.f32 %0, %1;" : "=f"(r) : "f"(x));
    return r;
}
__device__ __forceinline__ float sqrta(float x) {
    float r; asm("sqrt.approx.f32 %0, %1;" : "=f"(r) : "f"(x));
    return r;
}
// two kernel values (pixels u0,u1 at same bin), sqrt-weight folded:
//   sw2 * 1/(1 + u^2), f16x2 (1 MUFU per 2 values). u stays f32 for precision.
__device__ __forceinline__ unsigned kv(float u0, float u1, unsigned sw2) {
    unsigned u = pk(u0, u1);
    unsigned t;
    asm("fma.rn.f16x2 %0, %1, %1, %2;" : "=r"(t) : "r"(u), "r"(0x3C003C00u));
    __half2 th = *(__half2*)&t;
    __half2 rh = h2rcp(th);
    return hm2(*(unsigned*)&rh, sw2);
}
__device__ __forceinline__ void mma16816(float* c, const unsigned* a, unsigned b0, unsigned b1) {
    asm volatile(
        "mma.sync.aligned.m16n8k16.row.col.f32.f16.f16.f32 "
        "{%0,%1,%2,%3}, {%4,%5,%6,%7}, {%8,%9}, {%0,%1,%2,%3};"
        : "+f"(c[0]), "+f"(c[1]), "+f"(c[2]), "+f"(c[3])
        : "r"(a[0]), "r"(a[1]), "r"(a[2]), "r"(a[3]), "r"(b0), "r"(b1));
}
__device__ __forceinline__ float shf(float v, int src) {
    return __shfl_sync(0xffffffffu, v, src);
}

// 6 warps per CTA. Warp w: g = w%3 (vector/GEMM id), h = w/3 (pixel half).
// Fully decoupled until one sync: each warp loads all 3 channels of ITS 32
// pixels, computes d_g + sw locally, shuffles into fragment order, produces
// vec g's fragment image for K-steps {2h,2h+1} into the current buffer.
// One __syncthreads, then consumes GEMM g (A=img[g>>1], B=img[g?2:1]),
// N-columns [32h, 32h+32). Buffers alternate per chunk (WAR-safe: readers of
// buffer b have passed the next chunk's sync before b is rewritten).
__global__ __launch_bounds__(192, 3) void hist_main(const float* __restrict__ x) {
    __shared__ uint4 img[2][3 * 4 * 4 * 32];   // [buf][vec][st][mtile][lane], 48 KB

    const int tid = threadIdx.x;
    const int w = tid >> 5;
    const int L = tid & 31;
    const int g = w % 3, h = w / 3;
    const int bx = blockIdx.x;
    const int l = bx / NSPLIT, split = bx % NSPLIT;
    const int cbeg = (split * NCHUNKS) / NSPLIT;
    const int cend = ((split + 1) * NCHUNKS) / NSPLIT;
    const float* __restrict__ xp = x + (size_t)l * 3 * NPIX + 32 * h + L;

    float acc[4][4][4];
#pragma unroll
    for (int m = 0; m < 4; m++)
#pragma unroll
        for (int j = 0; j < 4; j++)
#pragma unroll
            for (int k = 0; k < 4; k++) acc[m][j][k] = 0.0f;

    const float DLT = (6.0f / 63.0f) * 50.0f;             // scaled bin spacing
    const float ro_base = -150.0f + (float)(L >> 2) * DLT;
    const float ro_step = 8.0f * DLT;
    const int q = L & 3;
    const int aimg = g >> 1;                  // A-operand image per GEMM
    const int bimg = (g == 0) ? 1 : 2;        // B-operand image per GEMM
    const float SC = 34.65735903f;            // ln(2)/sigma

    // prefetch first chunk (all 3 channels of this warp's 32 pixels)
    float pi0 = xp[(size_t)cbeg * 64];
    float pi1 = xp[(size_t)cbeg * 64 + NPIX];
    float pi2 = xp[(size_t)cbeg * 64 + 2 * NPIX];

    int buf = 0;
#pragma unroll 1
    for (int ch = cbeg; ch < cend; ch++) {
        float i0 = fminf(fmaxf(pi0, 0.0f), 1.0f);
        float i1 = fminf(fmaxf(pi1, 0.0f), 1.0f);
        float i2 = fminf(fmaxf(pi2, 0.0f), 1.0f);
        if (ch + 1 < cend) {                  // prefetch next chunk early
            pi0 = xp[(size_t)(ch + 1) * 64];
            pi1 = xp[(size_t)(ch + 1) * 64 + NPIX];
            pi2 = xp[(size_t)(ch + 1) * 64 + 2 * NPIX];
        }
        float l0 = lg2a(i0 + 1e-6f);
        float l1 = lg2a(i1 + 1e-6f);
        float l2 = lg2a(i2 + 1e-6f);
        float d = (g == 0) ? (l0 - l1) : (g == 1) ? (l0 - l2) : (l1 - l2);
        d *= SC;
        float s = fmaf(i0, i0, fmaf(i1, i1, fmaf(i2, i2, 1e-6f)));
        float sw = sqrta(sqrta(s));           // sqrt(Iy)

        // produce vec g's fragment image for K-steps 2h, 2h+1
        uint4* ib = img[buf];
#pragma unroll
        for (int si = 0; si < 2; si++) {
            const int st = 2 * h + si;
            const int b0 = 16 * si + 2 * q;
            float dA = shf(d, b0),     dB = shf(d, b0 + 1);
            float dC = shf(d, b0 + 8), dD = shf(d, b0 + 9);
            unsigned s0 = pk(shf(sw, b0),     shf(sw, b0 + 1));
            unsigned s1 = pk(shf(sw, b0 + 8), shf(sw, b0 + 9));
#pragma unroll
            for (int m = 0; m < 4; m++) {
                const float o0 = fmaf((float)(2 * m), ro_step, ro_base);
                const float o1 = o0 + ro_step;
                uint4 v;
                v.x = kv(dA - o0, dB - o0, s0);
                v.y = kv(dA - o1, dB - o1, s0);
                v.z = kv(dC - o0, dD - o0, s1);
                v.w = kv(dC - o1, dD - o1, s1);
                ib[((g * 4 + st) * 4 + m) * 32 + L] = v;
            }
        }
        __syncthreads();   // the ONLY barrier per chunk

        // consume — GEMM g, N-half h: 4 K-steps x 16 MMAs
#pragma unroll
        for (int st = 0; st < 4; st++) {
            uint4 A0 = ib[((aimg * 4 + st) * 4 + 0) * 32 + L];
            uint4 A1 = ib[((aimg * 4 + st) * 4 + 1) * 32 + L];
            uint4 A2 = ib[((aimg * 4 + st) * 4 + 2) * 32 + L];
            uint4 A3 = ib[((aimg * 4 + st) * 4 + 3) * 32 + L];
            uint4 W0 = ib[((bimg * 4 + st) * 4 + 2 * h) * 32 + L];
            uint4 W1 = ib[((bimg * 4 + st) * 4 + 2 * h + 1) * 32 + L];
            mma16816(acc[0][0], (const unsigned*)&A0, W0.x, W0.z);
            mma16816(acc[1][0], (const unsigned*)&A1, W0.x, W0.z);
            mma16816(acc[2][0], (const unsigned*)&A2, W0.x, W0.z);
            mma16816(acc[3][0], (const unsigned*)&A3, W0.x, W0.z);
            mma16816(acc[0][1], (const unsigned*)&A0, W0.y, W0.w);
            mma16816(acc[1][1], (const unsigned*)&A1, W0.y, W0.w);
            mma16816(acc[2][1], (const unsigned*)&A2, W0.y, W0.w);
            mma16816(acc[3][1], (const unsigned*)&A3, W0.y, W0.w);
            mma16816(acc[0][2], (const unsigned*)&A0, W1.x, W1.z);
            mma16816(acc[1][2], (const unsigned*)&A1, W1.x, W1.z);
            mma16816(acc[2][2], (const unsigned*)&A2, W1.x, W1.z);
            mma16816(acc[3][2], (const unsigned*)&A3, W1.x, W1.z);
            mma16816(acc[0][3], (const unsigned*)&A0, W1.y, W1.w);
            mma16816(acc[1][3], (const unsigned*)&A1, W1.y, W1.w);
            mma16816(acc[2][3], (const unsigned*)&A2, W1.y, W1.w);
            mma16816(acc[3][3], (const unsigned*)&A3, W1.y, W1.w);
        }
        buf ^= 1;
    }

    // store this warp's GEMM half-tile (non-atomic, private slot)
    float* dst = g_part + ((size_t)bx * 3 + g) * (H * H);
    const int r = L >> 2;
    const int qq = (L & 3) * 2;
#pragma unroll
    for (int m = 0; m < 4; m++)
#pragma unroll
        for (int jl = 0; jl < 4; jl++) {
            const int row0 = m * 16 + r;
            const int col = (4 * h + jl) * 8 + qq;
            *(float2*)(dst + row0 * H + col)       = make_float2(acc[m][jl][0], acc[m][jl][1]);
            *(float2*)(dst + (row0 + 8) * H + col) = make_float2(acc[m][jl][2], acc[m][jl][3]);
        }
}

// grid (16, 24), 256 threads. Sums NSPLIT splits with the channel reversal
// mapping, writes out and a per-block partial total (no atomics, no zeroing).
__global__ void hist_reduce(float* __restrict__ out) {
    const int lc = blockIdx.y;
    const int c = lc % 3, lidx = lc / 3;
    const int e = blockIdx.x * 256 + threadIdx.x;  // 0..4095
    const int u = e >> 6, v = e & 63;
    int se;
    if (c == 0)      se = e;                        // identity
    else if (c == 1) se = ((63 - u) << 6) | v;      // row reversal
    else             se = 4095 - e;                 // row+col reversal
    const float* __restrict__ src =
        g_part + ((size_t)(lidx * NSPLIT) * 3 + c) * (H * H) + se;
    float s = 0.0f;
#pragma unroll 5
    for (int sp = 0; sp < NSPLIT; sp++) s += src[(size_t)sp * 3 * (H * H)];
    out[lc * (H * H) + e] = s;

    __shared__ float red[256];
    red[threadIdx.x] = s;
    __syncthreads();
#pragma unroll
    for (int st = 128; st > 0; st >>= 1) {
        if (threadIdx.x < st) red[threadIdx.x] += red[threadIdx.x + st];
        __syncthreads();
    }
    if (threadIdx.x == 0)
        g_bsum[lc * 16 + blockIdx.x] = red[0];
}

// grid 384, 256 threads. Each block covers 256 contiguous outputs (same l).
__global__ void hist_norm(float* __restrict__ out) {
    __shared__ float red[48];
    const int l = blockIdx.x / 48;                  // 12288 per l / 256 = 48 blocks
    if (threadIdx.x < 48) red[threadIdx.x] = g_bsum[l * 48 + threadIdx.x];
    __syncthreads();
    float tot = 1e-6f;
#pragma unroll
    for (int k = 0; k < 48; k++) tot += red[k];
    const int idx = blockIdx.x * 256 + threadIdx.x;
    out[idx] = out[idx] / tot;
}

extern "C" void kernel_launch(void* const* d_in, const int* in_sizes, int n_in,
                              void* d_out, int out_size) {
    const float* x = (const float*)d_in[0];
    float* out = (float*)d_out;
    (void)in_sizes; (void)n_in; (void)out_size;

    hist_main<<<NCTA, 192>>>(x);
    hist_reduce<<<dim3(16, 24), 256>>>(out);
    hist_norm<<<384, 256>>>(out);
}

// round 9
// speedup vs baseline: 1.6197x; 1.0925x over previous
#include <cuda_runtime.h>
#include <cuda_fp16.h>
#include <cstdint>

#define H        64
#define NPIX     65536
#define LBATCH   8
#define NSPLIT   37                      // 8*37 = 296 CTAs = 148 SMs * 2 CTAs (1 wave)
#define NCTA     (LBATCH * NSPLIT)
#define NCHUNKS  512                     // 128-pixel chunks per image

// scratch: per-CTA 3 GEMM tiles: [cta][gemm][64*64]
__device__ float g_part[(size_t)NCTA * 3 * H * H];
// per-reduce-block partial totals: [lc][16 blocks]
__device__ float g_bsum[LBATCH * 3 * 16];

#define SMEM_BYTES (2 * 3 * 8 * 4 * 32 * 16)   // [buf][vec][st8][mtile][lane] uint4 = 96 KB

__device__ __forceinline__ unsigned pk(float lo, float hi) {  // f32x2 -> f16x2
    unsigned r; asm("cvt.rn.f16x2.f32 %0, %2, %1;" : "=r"(r) : "f"(lo), "f"(hi));
    return r;
}
__device__ __forceinline__ unsigned hm2(unsigned a, unsigned b) {
    unsigned r; asm("mul.rn.f16x2 %0, %1, %2;" : "=r"(r) : "r"(a), "r"(b));
    return r;
}
__device__ __forceinline__ float lg2a(float x) {
    float r; asm("lg2.approx.f32 %0, %1;" : "=f"(r) : "f"(x));
    return r;
}
__device__ __forceinline__ float sqrta(float x) {
    float r; asm("sqrt.approx.f32 %0, %1;" : "=f"(r) : "f"(x));
    return r;
}
// two kernel values (pixels u0,u1 at same bin), sqrt-weight folded:
//   sw2 * 1/(1 + u^2), f16x2 (1 MUFU per 2 values). u stays f32 for precision.
__device__ __forceinline__ unsigned kv(float u0, float u1, unsigned sw2) {
    unsigned u = pk(u0, u1);
    unsigned t;
    asm("fma.rn.f16x2 %0, %1, %1, %2;" : "=r"(t) : "r"(u), "r"(0x3C003C00u));
    __half2 th = *(__half2*)&t;
    __half2 rh = h2rcp(th);
    return hm2(*(unsigned*)&rh, sw2);
}
__device__ __forceinline__ void mma16816(float* c, const unsigned* a, unsigned b0, unsigned b1) {
    asm volatile(
        "mma.sync.aligned.m16n8k16.row.col.f32.f16.f16.f32 "
        "{%0,%1,%2,%3}, {%4,%5,%6,%7}, {%8,%9}, {%0,%1,%2,%3};"
        : "+f"(c[0]), "+f"(c[1]), "+f"(c[2]), "+f"(c[3])
        : "r"(a[0]), "r"(a[1]), "r"(a[2]), "r"(a[3]), "r"(b0), "r"(b1));
}
__device__ __forceinline__ float shf(float v, int src) {
    return __shfl_sync(0xffffffffu, v, src);
}

// 12 warps per CTA. Warp w: g = w%3 (vector/GEMM id), h = w/3 in 0..3 (pixel quarter).
// 128-px chunks. Each warp loads all 3 channels of ITS 32 pixels, computes d_g + sw
// locally, shuffles into fragment order, produces vec g's fragment image for K-steps
// {2h, 2h+1} into the current buffer. One __syncthreads, then consumes GEMM g
// (A=img[g>>1], B=img[g?2:1]) restricted to N-columns [16h, 16h+16) -> acc[4][2][4]
// (32 regs). Buffers alternate per chunk (WAR-safe across the single barrier).
__global__ __launch_bounds__(384, 2) void hist_main(const float* __restrict__ x) {
    extern __shared__ uint4 img[];          // [2][3][8][4][32]

    const int tid = threadIdx.x;
    const int w = tid >> 5;
    const int L = tid & 31;
    const int g = w % 3, h = w / 3;
    const int bx = blockIdx.x;
    const int l = bx / NSPLIT, split = bx % NSPLIT;
    const int cbeg = (split * NCHUNKS) / NSPLIT;
    const int cend = ((split + 1) * NCHUNKS) / NSPLIT;
    const float* __restrict__ xp = x + (size_t)l * 3 * NPIX + 32 * h + L;

    float acc[4][2][4];
#pragma unroll
    for (int m = 0; m < 4; m++)
#pragma unroll
        for (int j = 0; j < 2; j++)
#pragma unroll
            for (int k = 0; k < 4; k++) acc[m][j][k] = 0.0f;

    const float DLT = (6.0f / 63.0f) * 50.0f;             // scaled bin spacing
    const float ro_base = -150.0f + (float)(L >> 2) * DLT;
    const float ro_step = 8.0f * DLT;
    const int q = L & 3;
    const int aimg = g >> 1;                  // A-operand image per GEMM
    const int bimg = (g == 0) ? 1 : 2;        // B-operand image per GEMM
    const float SC = 34.65735903f;            // ln(2)/sigma

    // prefetch first chunk (all 3 channels of this warp's 32 pixels)
    float pi0 = xp[(size_t)cbeg * 128];
    float pi1 = xp[(size_t)cbeg * 128 + NPIX];
    float pi2 = xp[(size_t)cbeg * 128 + 2 * NPIX];

    int buf = 0;
#pragma unroll 1
    for (int ch = cbeg; ch < cend; ch++) {
        float i0 = fminf(fmaxf(pi0, 0.0f), 1.0f);
        float i1 = fminf(fmaxf(pi1, 0.0f), 1.0f);
        float i2 = fminf(fmaxf(pi2, 0.0f), 1.0f);
        if (ch + 1 < cend) {                  // prefetch next chunk early
            pi0 = xp[(size_t)(ch + 1) * 128];
            pi1 = xp[(size_t)(ch + 1) * 128 + NPIX];
            pi2 = xp[(size_t)(ch + 1) * 128 + 2 * NPIX];
        }
        float l0 = lg2a(i0 + 1e-6f);
        float l1 = lg2a(i1 + 1e-6f);
        float l2 = lg2a(i2 + 1e-6f);
        float d = (g == 0) ? (l0 - l1) : (g == 1) ? (l0 - l2) : (l1 - l2);
        d *= SC;
        float s = fmaf(i0, i0, fmaf(i1, i1, fmaf(i2, i2, 1e-6f)));
        float sw = sqrta(sqrta(s));           // sqrt(Iy)

        uint4* ib = img + buf * (3 * 8 * 4 * 32);
        // produce vec g's fragment image for K-steps 2h, 2h+1
#pragma unroll
        for (int si = 0; si < 2; si++) {
            const int st = 2 * h + si;
            const int b0 = 16 * si + 2 * q;
            float dA = shf(d, b0),     dB = shf(d, b0 + 1);
            float dC = shf(d, b0 + 8), dD = shf(d, b0 + 9);
            unsigned s0 = pk(shf(sw, b0),     shf(sw, b0 + 1));
            unsigned s1 = pk(shf(sw, b0 + 8), shf(sw, b0 + 9));
#pragma unroll
            for (int m = 0; m < 4; m++) {
                const float o0 = fmaf((float)(2 * m), ro_step, ro_base);
                const float o1 = o0 + ro_step;
                uint4 v;
                v.x = kv(dA - o0, dB - o0, s0);
                v.y = kv(dA - o1, dB - o1, s0);
                v.z = kv(dC - o0, dD - o0, s1);
                v.w = kv(dC - o1, dD - o1, s1);
                ib[((g * 8 + st) * 4 + m) * 32 + L] = v;
            }
        }
        __syncthreads();   // the ONLY barrier per chunk

        // consume — GEMM g, N-quarter h: 8 K-steps x 8 MMAs
#pragma unroll
        for (int st = 0; st < 8; st++) {
            uint4 A0 = ib[((aimg * 8 + st) * 4 + 0) * 32 + L];
            uint4 A1 = ib[((aimg * 8 + st) * 4 + 1) * 32 + L];
            uint4 A2 = ib[((aimg * 8 + st) * 4 + 2) * 32 + L];
            uint4 A3 = ib[((aimg * 8 + st) * 4 + 3) * 32 + L];
            uint4 W  = ib[((bimg * 8 + st) * 4 + h) * 32 + L];  // jtiles 2h, 2h+1
            mma16816(acc[0][0], (const unsigned*)&A0, W.x, W.z);
            mma16816(acc[1][0], (const unsigned*)&A1, W.x, W.z);
            mma16816(acc[2][0], (const unsigned*)&A2, W.x, W.z);
            mma16816(acc[3][0], (const unsigned*)&A3, W.x, W.z);
            mma16816(acc[0][1], (const unsigned*)&A0, W.y, W.w);
            mma16816(acc[1][1], (const unsigned*)&A1, W.y, W.w);
            mma16816(acc[2][1], (const unsigned*)&A2, W.y, W.w);
            mma16816(acc[3][1], (const unsigned*)&A3, W.y, W.w);
        }
        buf ^= 1;
    }

    // store this warp's GEMM quarter-tile (non-atomic, private slot)
    float* dst = g_part + ((size_t)bx * 3 + g) * (H * H);
    const int r = L >> 2;
    const int qq = (L & 3) * 2;
#pragma unroll
    for (int m = 0; m < 4; m++)
#pragma unroll
        for (int jl = 0; jl < 2; jl++) {
            const int row0 = m * 16 + r;
            const int col = (2 * h + jl) * 8 + qq;
            *(float2*)(dst + row0 * H + col)       = make_float2(acc[m][jl][0], acc[m][jl][1]);
            *(float2*)(dst + (row0 + 8) * H + col) = make_float2(acc[m][jl][2], acc[m][jl][3]);
        }
}

// grid (16, 24), 256 threads. Sums NSPLIT splits with the channel reversal
// mapping, writes out and a per-block partial total (no atomics, no zeroing).
__global__ void hist_reduce(float* __restrict__ out) {
    const int lc = blockIdx.y;
    const int c = lc % 3, lidx = lc / 3;
    const int e = blockIdx.x * 256 + threadIdx.x;  // 0..4095
    const int u = e >> 6, v = e & 63;
    int se;
    if (c == 0)      se = e;                        // identity
    else if (c == 1) se = ((63 - u) << 6) | v;      // row reversal
    else             se = 4095 - e;                 // row+col reversal
    const float* __restrict__ src =
        g_part + ((size_t)(lidx * NSPLIT) * 3 + c) * (H * H) + se;
    float s = 0.0f;
#pragma unroll 2
    for (int sp = 0; sp < NSPLIT; sp++) s += src[(size_t)sp * 3 * (H * H)];
    out[lc * (H * H) + e] = s;

    __shared__ float red[256];
    red[threadIdx.x] = s;
    __syncthreads();
#pragma unroll
    for (int st = 128; st > 0; st >>= 1) {
        if (threadIdx.x < st) red[threadIdx.x] += red[threadIdx.x + st];
        __syncthreads();
    }
    if (threadIdx.x == 0)
        g_bsum[lc * 16 + blockIdx.x] = red[0];
}

// grid 384, 256 threads. Each block covers 256 contiguous outputs (same l).
__global__ void hist_norm(float* __restrict__ out) {
    __shared__ float red[48];
    const int l = blockIdx.x / 48;                  // 12288 per l / 256 = 48 blocks
    if (threadIdx.x < 48) red[threadIdx.x] = g_bsum[l * 48 + threadIdx.x];
    __syncthreads();
    float tot = 1e-6f;
#pragma unroll
    for (int k = 0; k < 48; k++) tot += red[k];
    const int idx = blockIdx.x * 256 + threadIdx.x;
    out[idx] = out[idx] / tot;
}

extern "C" void kernel_launch(void* const* d_in, const int* in_sizes, int n_in,
                              void* d_out, int out_size) {
    const float* x = (const float*)d_in[0];
    float* out = (float*)d_out;
    (void)in_sizes; (void)n_in; (void)out_size;

    cudaFuncSetAttribute(hist_main, cudaFuncAttributeMaxDynamicSharedMemorySize,
                         SMEM_BYTES);
    hist_main<<<NCTA, 384, SMEM_BYTES>>>(x);
    hist_reduce<<<dim3(16, 24), 256>>>(out);
    hist_norm<<<384, 256>>>(out);
}

// round 10
// speedup vs baseline: 1.6732x; 1.0330x over previous
#include <cuda_runtime.h>
#include <cuda_fp16.h>
#include <cstdint>

#define H        64
#define NPIX     65536
#define LBATCH   8
#define NSPLIT   37                      // 8*37 = 296 CTAs = 148 SMs * 2 CTAs (1 wave)
#define NCTA     (LBATCH * NSPLIT)
#define NCHUNKS  512                     // 128-pixel chunks per image

// scratch: per-CTA 3 GEMM tiles: [cta][gemm][64*64]
__device__ float g_part[(size_t)NCTA * 3 * H * H];
// per-reduce-block partial totals: [lc][16 blocks]
__device__ float g_bsum[LBATCH * 3 * 16];

#define SMEM_BYTES (2 * 3 * 8 * 4 * 32 * 16)   // [buf][vec][st8][mtile][lane] uint4 = 96 KB

__device__ __forceinline__ unsigned pk(float lo, float hi) {  // f32x2 -> f16x2
    unsigned r; asm("cvt.rn.f16x2.f32 %0, %2, %1;" : "=r"(r) : "f"(lo), "f"(hi));
    return r;
}
__device__ __forceinline__ unsigned hm2(unsigned a, unsigned b) {
    unsigned r; asm("mul.rn.f16x2 %0, %1, %2;" : "=r"(r) : "r"(a), "r"(b));
    return r;
}
__device__ __forceinline__ float lg2a(float x) {
    float r; asm("lg2.approx.f32 %0, %1;" : "=f"(r) : "f"(x));
    return r;
}
__device__ __forceinline__ float sqrta(float x) {
    float r; asm("sqrt.approx.f32 %0, %1;" : "=f"(r) : "f"(x));
    return r;
}
// two kernel values (pixels u0,u1 at same bin), sqrt-weight folded:
//   sw2 * 1/(1 + u^2), f16x2 (1 MUFU per 2 values). u stays f32 for precision.
__device__ __forceinline__ unsigned kv(float u0, float u1, unsigned sw2) {
    unsigned u = pk(u0, u1);
    unsigned t;
    asm("fma.rn.f16x2 %0, %1, %1, %2;" : "=r"(t) : "r"(u), "r"(0x3C003C00u));
    __half2 th = *(__half2*)&t;
    __half2 rh = h2rcp(th);
    return hm2(*(unsigned*)&rh, sw2);
}
__device__ __forceinline__ void mma16816(float* c, const unsigned* a, unsigned b0, unsigned b1) {
    asm volatile(
        "mma.sync.aligned.m16n8k16.row.col.f32.f16.f16.f32 "
        "{%0,%1,%2,%3}, {%4,%5,%6,%7}, {%8,%9}, {%0,%1,%2,%3};"
        : "+f"(c[0]), "+f"(c[1]), "+f"(c[2]), "+f"(c[3])
        : "r"(a[0]), "r"(a[1]), "r"(a[2]), "r"(a[3]), "r"(b0), "r"(b1));
}
__device__ __forceinline__ float shf(float v, int src) {
    return __shfl_sync(0xffffffffu, v, src);
}

// 12 warps per CTA. Warp w: g = w%3 (vector/GEMM id), h = w/3 in 0..3.
// 128-px chunks. Produce: each warp loads all 3 channels of ITS 32 pixels
// (quarter h), computes d_g + sw locally, shuffles into fragment order,
// produces vec g's fragment image for K-steps {2h, 2h+1}. One __syncthreads,
// then consume: GEMM g (A=img[g>>1], B=img[g?2:1]) split 2x2 — warp (g,h)
// with mi=h>>1, ni=h&1 computes the 32x32 quadrant (mtiles {2mi,2mi+1},
// jtiles {4ni..4ni+3}): per K-step 2 A-frag + 2 B-frag LDS.128 for 8 MMAs.
// acc[2][4][4] = 32 regs. Buffers alternate per chunk (WAR-safe).
__global__ __launch_bounds__(384, 2) void hist_main(const float* __restrict__ x) {
    extern __shared__ uint4 img[];          // [2][3][8][4][32]

    const int tid = threadIdx.x;
    const int w = tid >> 5;
    const int L = tid & 31;
    const int g = w % 3, h = w / 3;
    const int mi = h >> 1, ni = h & 1;
    const int bx = blockIdx.x;
    const int l = bx / NSPLIT, split = bx % NSPLIT;
    const int cbeg = (split * NCHUNKS) / NSPLIT;
    const int cend = ((split + 1) * NCHUNKS) / NSPLIT;
    const float* __restrict__ xp = x + (size_t)l * 3 * NPIX + 32 * h + L;

    float acc[2][4][4];
#pragma unroll
    for (int m = 0; m < 2; m++)
#pragma unroll
        for (int j = 0; j < 4; j++)
#pragma unroll
            for (int k = 0; k < 4; k++) acc[m][j][k] = 0.0f;

    const float DLT = (6.0f / 63.0f) * 50.0f;             // scaled bin spacing
    const float ro_base = -150.0f + (float)(L >> 2) * DLT;
    const float ro_step = 8.0f * DLT;
    const int q = L & 3;
    const int aimg = g >> 1;                  // A-operand image per GEMM
    const int bimg = (g == 0) ? 1 : 2;        // B-operand image per GEMM
    const float SC = 34.65735903f;            // ln(2)/sigma

    // prefetch first chunk (all 3 channels of this warp's 32 pixels)
    float pi0 = xp[(size_t)cbeg * 128];
    float pi1 = xp[(size_t)cbeg * 128 + NPIX];
    float pi2 = xp[(size_t)cbeg * 128 + 2 * NPIX];

    int buf = 0;
#pragma unroll 1
    for (int ch = cbeg; ch < cend; ch++) {
        float i0 = fminf(fmaxf(pi0, 0.0f), 1.0f);
        float i1 = fminf(fmaxf(pi1, 0.0f), 1.0f);
        float i2 = fminf(fmaxf(pi2, 0.0f), 1.0f);
        if (ch + 1 < cend) {                  // prefetch next chunk early
            pi0 = xp[(size_t)(ch + 1) * 128];
            pi1 = xp[(size_t)(ch + 1) * 128 + NPIX];
            pi2 = xp[(size_t)(ch + 1) * 128 + 2 * NPIX];
        }
        float l0 = lg2a(i0 + 1e-6f);
        float l1 = lg2a(i1 + 1e-6f);
        float l2 = lg2a(i2 + 1e-6f);
        float d = (g == 0) ? (l0 - l1) : (g == 1) ? (l0 - l2) : (l1 - l2);
        d *= SC;
        float s = fmaf(i0, i0, fmaf(i1, i1, fmaf(i2, i2, 1e-6f)));
        float sw = sqrta(sqrta(s));           // sqrt(Iy)

        uint4* ib = img + buf * (3 * 8 * 4 * 32);
        // produce vec g's fragment image for K-steps 2h, 2h+1
#pragma unroll
        for (int si = 0; si < 2; si++) {
            const int st = 2 * h + si;
            const int b0 = 16 * si + 2 * q;
            float dA = shf(d, b0),     dB = shf(d, b0 + 1);
            float dC = shf(d, b0 + 8), dD = shf(d, b0 + 9);
            unsigned s0 = pk(shf(sw, b0),     shf(sw, b0 + 1));
            unsigned s1 = pk(shf(sw, b0 + 8), shf(sw, b0 + 9));
#pragma unroll
            for (int m = 0; m < 4; m++) {
                const float o0 = fmaf((float)(2 * m), ro_step, ro_base);
                const float o1 = o0 + ro_step;
                uint4 v;
                v.x = kv(dA - o0, dB - o0, s0);
                v.y = kv(dA - o1, dB - o1, s0);
                v.z = kv(dC - o0, dD - o0, s1);
                v.w = kv(dC - o1, dD - o1, s1);
                ib[((g * 8 + st) * 4 + m) * 32 + L] = v;
            }
        }
        __syncthreads();   // the ONLY barrier per chunk

        // consume — GEMM g quadrant (mi, ni): 8 K-steps x 8 MMAs, 4 LDS each
#pragma unroll
        for (int st = 0; st < 8; st++) {
            uint4 A0 = ib[((aimg * 8 + st) * 4 + 2 * mi) * 32 + L];
            uint4 A1 = ib[((aimg * 8 + st) * 4 + 2 * mi + 1) * 32 + L];
            uint4 W0 = ib[((bimg * 8 + st) * 4 + 2 * ni) * 32 + L];     // jtiles 4ni, 4ni+1
            uint4 W1 = ib[((bimg * 8 + st) * 4 + 2 * ni + 1) * 32 + L]; // jtiles 4ni+2, 4ni+3
            mma16816(acc[0][0], (const unsigned*)&A0, W0.x, W0.z);
            mma16816(acc[1][0], (const unsigned*)&A1, W0.x, W0.z);
            mma16816(acc[0][1], (const unsigned*)&A0, W0.y, W0.w);
            mma16816(acc[1][1], (const unsigned*)&A1, W0.y, W0.w);
            mma16816(acc[0][2], (const unsigned*)&A0, W1.x, W1.z);
            mma16816(acc[1][2], (const unsigned*)&A1, W1.x, W1.z);
            mma16816(acc[0][3], (const unsigned*)&A0, W1.y, W1.w);
            mma16816(acc[1][3], (const unsigned*)&A1, W1.y, W1.w);
        }
        buf ^= 1;
    }

    // store this warp's 32x32 quadrant (non-atomic, private slot)
    float* dst = g_part + ((size_t)bx * 3 + g) * (H * H);
    const int r = L >> 2;
    const int qq = (L & 3) * 2;
#pragma unroll
    for (int m = 0; m < 2; m++)
#pragma unroll
        for (int jl = 0; jl < 4; jl++) {
            const int row0 = (2 * mi + m) * 16 + r;
            const int col = (4 * ni + jl) * 8 + qq;
            *(float2*)(dst + row0 * H + col)       = make_float2(acc[m][jl][0], acc[m][jl][1]);
            *(float2*)(dst + (row0 + 8) * H + col) = make_float2(acc[m][jl][2], acc[m][jl][3]);
        }
}

// grid (16, 24), 256 threads. Sums NSPLIT splits with the channel reversal
// mapping, writes out and a per-block partial total (no atomics, no zeroing).
__global__ void hist_reduce(float* __restrict__ out) {
    const int lc = blockIdx.y;
    const int c = lc % 3, lidx = lc / 3;
    const int e = blockIdx.x * 256 + threadIdx.x;  // 0..4095
    const int u = e >> 6, v = e & 63;
    int se;
    if (c == 0)      se = e;                        // identity
    else if (c == 1) se = ((63 - u) << 6) | v;      // row reversal
    else             se = 4095 - e;                 // row+col reversal
    const float* __restrict__ src =
        g_part + ((size_t)(lidx * NSPLIT) * 3 + c) * (H * H) + se;
    float s0 = 0.0f, s1 = 0.0f, s2 = 0.0f, s3 = 0.0f;
    int sp = 0;
#pragma unroll 1
    for (; sp + 4 <= NSPLIT; sp += 4) {
        s0 += src[(size_t)(sp + 0) * 3 * (H * H)];
        s1 += src[(size_t)(sp + 1) * 3 * (H * H)];
        s2 += src[(size_t)(sp + 2) * 3 * (H * H)];
        s3 += src[(size_t)(sp + 3) * 3 * (H * H)];
    }
    for (; sp < NSPLIT; sp++) s0 += src[(size_t)sp * 3 * (H * H)];
    float s = (s0 + s1) + (s2 + s3);
    out[lc * (H * H) + e] = s;

    __shared__ float red[256];
    red[threadIdx.x] = s;
    __syncthreads();
#pragma unroll
    for (int st = 128; st > 0; st >>= 1) {
        if (threadIdx.x < st) red[threadIdx.x] += red[threadIdx.x + st];
        __syncthreads();
    }
    if (threadIdx.x == 0)
        g_bsum[lc * 16 + blockIdx.x] = red[0];
}

// grid 384, 256 threads. Each block covers 256 contiguous outputs (same l).
__global__ void hist_norm(float* __restrict__ out) {
    __shared__ float red[48];
    const int l = blockIdx.x / 48;                  // 12288 per l / 256 = 48 blocks
    if (threadIdx.x < 48) red[threadIdx.x] = g_bsum[l * 48 + threadIdx.x];
    __syncthreads();
    float tot = 1e-6f;
#pragma unroll
    for (int k = 0; k < 48; k++) tot += red[k];
    const int idx = blockIdx.x * 256 + threadIdx.x;
    out[idx] = out[idx] / tot;
}

extern "C" void kernel_launch(void* const* d_in, const int* in_sizes, int n_in,
                              void* d_out, int out_size) {
    const float* x = (const float*)d_in[0];
    float* out = (float*)d_out;
    (void)in_sizes; (void)n_in; (void)out_size;

    cudaFuncSetAttribute(hist_main, cudaFuncAttributeMaxDynamicSharedMemorySize,
                         SMEM_BYTES);
    hist_main<<<NCTA, 384, SMEM_BYTES>>>(x);
    hist_reduce<<<dim3(16, 24), 256>>>(out);
    hist_norm<<<384, 256>>>(out);
}

// round 11
// speedup vs baseline: 1.6952x; 1.0132x over previous
#include <cuda_runtime.h>
#include <cuda_fp16.h>
#include <cstdint>

#define H        64
#define NPIX     65536
#define LBATCH   8
#define NSPLIT   37                      // 8*37 = 296 CTAs = 148 SMs * 2 CTAs (1 wave)
#define NCTA     (LBATCH * NSPLIT)
#define NCHUNKS  512                     // 128-pixel chunks per image

// scratch: per-CTA 3 GEMM tiles: [cta][gemm][64*64]
__device__ float g_part[(size_t)NCTA * 3 * H * H];
// per-reduce-block partial totals: [lc][16 blocks]
__device__ float g_bsum[LBATCH * 3 * 16];

#define IMG_U4   (3 * 8 * 4 * 32)              // uint4s per buffer
#define SMEM_BYTES (2 * IMG_U4 * 16)           // 96 KB

__device__ __forceinline__ unsigned pk(float lo, float hi) {  // f32x2 -> f16x2
    unsigned r; asm("cvt.rn.f16x2.f32 %0, %2, %1;" : "=r"(r) : "f"(lo), "f"(hi));
    return r;
}
__device__ __forceinline__ unsigned hm2(unsigned a, unsigned b) {
    unsigned r; asm("mul.rn.f16x2 %0, %1, %2;" : "=r"(r) : "r"(a), "r"(b));
    return r;
}
__device__ __forceinline__ float lg2a(float x) {
    float r; asm("lg2.approx.f32 %0, %1;" : "=f"(r) : "f"(x));
    return r;
}
__device__ __forceinline__ float sqrta(float x) {
    float r; asm("sqrt.approx.f32 %0, %1;" : "=f"(r) : "f"(x));
    return r;
}
// two kernel values (pixels u0,u1 at same bin), sqrt-weight folded:
//   sw2 * 1/(1 + u^2), f16x2 (1 MUFU per 2 values). u stays f32 for precision.
__device__ __forceinline__ unsigned kv(float u0, float u1, unsigned sw2) {
    unsigned u = pk(u0, u1);
    unsigned t;
    asm("fma.rn.f16x2 %0, %1, %1, %2;" : "=r"(t) : "r"(u), "r"(0x3C003C00u));
    __half2 th = *(__half2*)&t;
    __half2 rh = h2rcp(th);
    return hm2(*(unsigned*)&rh, sw2);
}
__device__ __forceinline__ void mma16816(float* c, const unsigned* a, unsigned b0, unsigned b1) {
    asm volatile(
        "mma.sync.aligned.m16n8k16.row.col.f32.f16.f16.f32 "
        "{%0,%1,%2,%3}, {%4,%5,%6,%7}, {%8,%9}, {%0,%1,%2,%3};"
        : "+f"(c[0]), "+f"(c[1]), "+f"(c[2]), "+f"(c[3])
        : "r"(a[0]), "r"(a[1]), "r"(a[2]), "r"(a[3]), "r"(b0), "r"(b1));
}
__device__ __forceinline__ float shf(float v, int src) {
    return __shfl_sync(0xffffffffu, v, src);
}

// 12 warps per CTA. Warp w: g = w%3 (vector/GEMM id), h = w/3 in 0..3.
// 128-px chunks. Software-pipelined: region r = [interleaved consume(chunk r,
// buf r&1) + prep/produce(chunk r+1, buf (r&1)^1)], one barrier per region.
// Produce: warp loads all 3 channels of ITS 32 pixels, computes d_g + sw,
// shuffles into fragment order, emits vec g's fragments for K-steps {2h,2h+1}.
// Consume: GEMM g (A=img[g>>1], B=img[g?2:1]) split 2x2 — warp quadrant
// (mi,ni), per K-step 2 A-frag + 2 B-frag LDS.128 for 8 MMAs. acc = 32 regs.
__global__ __launch_bounds__(384, 2) void hist_main(const float* __restrict__ x) {
    extern __shared__ uint4 img[];          // [2][3][8][4][32]

    const int tid = threadIdx.x;
    const int w = tid >> 5;
    const int L = tid & 31;
    const int g = w % 3, h = w / 3;
    const int mi = h >> 1, ni = h & 1;
    const int bx = blockIdx.x;
    const int l = bx / NSPLIT, split = bx % NSPLIT;
    const int cbeg = (split * NCHUNKS) / NSPLIT;
    const int cend = ((split + 1) * NCHUNKS) / NSPLIT;
    const float* __restrict__ xp = x + (size_t)l * 3 * NPIX + 32 * h + L;

    float acc[2][4][4];
#pragma unroll
    for (int m = 0; m < 2; m++)
#pragma unroll
        for (int j = 0; j < 4; j++)
#pragma unroll
            for (int k = 0; k < 4; k++) acc[m][j][k] = 0.0f;

    const float DLT = (6.0f / 63.0f) * 50.0f;             // scaled bin spacing
    const float ro_base = -150.0f + (float)(L >> 2) * DLT;
    const float ro_step = 8.0f * DLT;
    const int q = L & 3;
    const int aimg = g >> 1;                  // A-operand image per GEMM
    const int bimg = (g == 0) ? 1 : 2;        // B-operand image per GEMM
    const float SC = 34.65735903f;            // ln(2)/sigma

    // prefetch first chunk (all 3 channels of this warp's 32 pixels)
    float pi0 = xp[(size_t)cbeg * 128];
    float pi1 = xp[(size_t)cbeg * 128 + NPIX];
    float pi2 = xp[(size_t)cbeg * 128 + 2 * NPIX];

    float pd[8];        // fragment-ordered d values, [si][4]
    unsigned ps[4];     // fragment-ordered packed sqrt-weights, [si][2]

    // prep(ch): consume prefetched pi*, prefetch ch+1, fill pd/ps
    auto prep = [&](int ch) {
        float i0 = fminf(fmaxf(pi0, 0.0f), 1.0f);
        float i1 = fminf(fmaxf(pi1, 0.0f), 1.0f);
        float i2 = fminf(fmaxf(pi2, 0.0f), 1.0f);
        if (ch + 1 < cend) {
            pi0 = xp[(size_t)(ch + 1) * 128];
            pi1 = xp[(size_t)(ch + 1) * 128 + NPIX];
            pi2 = xp[(size_t)(ch + 1) * 128 + 2 * NPIX];
        }
        float l0 = lg2a(i0 + 1e-6f);
        float l1 = lg2a(i1 + 1e-6f);
        float l2 = lg2a(i2 + 1e-6f);
        float d = (g == 0) ? (l0 - l1) : (g == 1) ? (l0 - l2) : (l1 - l2);
        d *= SC;
        float s = fmaf(i0, i0, fmaf(i1, i1, fmaf(i2, i2, 1e-6f)));
        float sw = sqrta(sqrta(s));           // sqrt(Iy)
#pragma unroll
        for (int si = 0; si < 2; si++) {
            const int b0 = 16 * si + 2 * q;
            pd[4 * si + 0] = shf(d, b0);
            pd[4 * si + 1] = shf(d, b0 + 1);
            pd[4 * si + 2] = shf(d, b0 + 8);
            pd[4 * si + 3] = shf(d, b0 + 9);
            ps[2 * si + 0] = pk(shf(sw, b0),     shf(sw, b0 + 1));
            ps[2 * si + 1] = pk(shf(sw, b0 + 8), shf(sw, b0 + 9));
        }
    };
    // produce block k (si=k>>2, m=k&3) into buffer ib_p
    auto produce = [&](int k, uint4* ib_p) {
        const int si = k >> 2, m = k & 3;
        const float o0 = fmaf((float)(2 * m), ro_step, ro_base);
        const float o1 = o0 + ro_step;
        uint4 v;
        v.x = kv(pd[4 * si + 0] - o0, pd[4 * si + 1] - o0, ps[2 * si]);
        v.y = kv(pd[4 * si + 0] - o1, pd[4 * si + 1] - o1, ps[2 * si]);
        v.z = kv(pd[4 * si + 2] - o0, pd[4 * si + 3] - o0, ps[2 * si + 1]);
        v.w = kv(pd[4 * si + 2] - o1, pd[4 * si + 3] - o1, ps[2 * si + 1]);
        ib_p[((g * 8 + 2 * h + si) * 4 + m) * 32 + L] = v;
    };
    // consume K-step st from buffer ib_c
    auto consume = [&](int st, const uint4* ib_c) {
        uint4 A0 = ib_c[((aimg * 8 + st) * 4 + 2 * mi) * 32 + L];
        uint4 A1 = ib_c[((aimg * 8 + st) * 4 + 2 * mi + 1) * 32 + L];
        uint4 W0 = ib_c[((bimg * 8 + st) * 4 + 2 * ni) * 32 + L];
        uint4 W1 = ib_c[((bimg * 8 + st) * 4 + 2 * ni + 1) * 32 + L];
        mma16816(acc[0][0], (const unsigned*)&A0, W0.x, W0.z);
        mma16816(acc[1][0], (const unsigned*)&A1, W0.x, W0.z);
        mma16816(acc[0][1], (const unsigned*)&A0, W0.y, W0.w);
        mma16816(acc[1][1], (const unsigned*)&A1, W0.y, W0.w);
        mma16816(acc[0][2], (const unsigned*)&A0, W1.x, W1.z);
        mma16816(acc[1][2], (const unsigned*)&A1, W1.x, W1.z);
        mma16816(acc[0][3], (const unsigned*)&A0, W1.y, W1.w);
        mma16816(acc[1][3], (const unsigned*)&A1, W1.y, W1.w);
    };

    const int nreg = cend - cbeg;
    // prologue: produce chunk cbeg into buf 0
    prep(cbeg);
#pragma unroll
    for (int k = 0; k < 8; k++) produce(k, img);
    __syncthreads();

#pragma unroll 1
    for (int r = 0; r < nreg - 1; r++) {
        const uint4* ib_c = img + (r & 1) * IMG_U4;
        uint4* ib_p = img + ((r & 1) ^ 1) * IMG_U4;
        prep(cbeg + r + 1);
#pragma unroll
        for (int k = 0; k < 8; k++) {    // interleave tensor + mufu/fma work
            consume(k, ib_c);
            produce(k, ib_p);
        }
        __syncthreads();
    }
    // final region: consume only
    {
        const uint4* ib_c = img + ((nreg - 1) & 1) * IMG_U4;
#pragma unroll
        for (int k = 0; k < 8; k++) consume(k, ib_c);
    }

    // store this warp's 32x32 quadrant (non-atomic, private slot)
    float* dst = g_part + ((size_t)bx * 3 + g) * (H * H);
    const int r = L >> 2;
    const int qq = (L & 3) * 2;
#pragma unroll
    for (int m = 0; m < 2; m++)
#pragma unroll
        for (int jl = 0; jl < 4; jl++) {
            const int row0 = (2 * mi + m) * 16 + r;
            const int col = (4 * ni + jl) * 8 + qq;
            *(float2*)(dst + row0 * H + col)       = make_float2(acc[m][jl][0], acc[m][jl][1]);
            *(float2*)(dst + (row0 + 8) * H + col) = make_float2(acc[m][jl][2], acc[m][jl][3]);
        }
}

// grid (16, 24), 256 threads. Sums NSPLIT splits with the channel reversal
// mapping, writes out and a per-block partial total (no atomics, no zeroing).
__global__ void hist_reduce(float* __restrict__ out) {
    const int lc = blockIdx.y;
    const int c = lc % 3, lidx = lc / 3;
    const int e = blockIdx.x * 256 + threadIdx.x;  // 0..4095
    const int u = e >> 6, v = e & 63;
    int se;
    if (c == 0)      se = e;                        // identity
    else if (c == 1) se = ((63 - u) << 6) | v;      // row reversal
    else             se = 4095 - e;                 // row+col reversal
    const float* __restrict__ src =
        g_part + ((size_t)(lidx * NSPLIT) * 3 + c) * (H * H) + se;
    float s0 = 0.0f, s1 = 0.0f, s2 = 0.0f, s3 = 0.0f;
    int sp = 0;
#pragma unroll 1
    for (; sp + 4 <= NSPLIT; sp += 4) {
        s0 += src[(size_t)(sp + 0) * 3 * (H * H)];
        s1 += src[(size_t)(sp + 1) * 3 * (H * H)];
        s2 += src[(size_t)(sp + 2) * 3 * (H * H)];
        s3 += src[(size_t)(sp + 3) * 3 * (H * H)];
    }
    for (; sp < NSPLIT; sp++) s0 += src[(size_t)sp * 3 * (H * H)];
    float s = (s0 + s1) + (s2 + s3);
    out[lc * (H * H) + e] = s;

    __shared__ float red[256];
    red[threadIdx.x] = s;
    __syncthreads();
#pragma unroll
    for (int st = 128; st > 0; st >>= 1) {
        if (threadIdx.x < st) red[threadIdx.x] += red[threadIdx.x + st];
        __syncthreads();
    }
    if (threadIdx.x == 0)
        g_bsum[lc * 16 + blockIdx.x] = red[0];
}

// grid 384, 256 threads. Each block covers 256 contiguous outputs (same l).
__global__ void hist_norm(float* __restrict__ out) {
    __shared__ float red[48];
    const int l = blockIdx.x / 48;                  // 12288 per l / 256 = 48 blocks
    if (threadIdx.x < 48) red[threadIdx.x] = g_bsum[l * 48 + threadIdx.x];
    __syncthreads();
    float tot = 1e-6f;
#pragma unroll
    for (int k = 0; k < 48; k++) tot += red[k];
    const int idx = blockIdx.x * 256 + threadIdx.x;
    out[idx] = out[idx] / tot;
}

extern "C" void kernel_launch(void* const* d_in, const int* in_sizes, int n_in,
                              void* d_out, int out_size) {
    const float* x = (const float*)d_in[0];
    float* out = (float*)d_out;
    (void)in_sizes; (void)n_in; (void)out_size;

    cudaFuncSetAttribute(hist_main, cudaFuncAttributeMaxDynamicSharedMemorySize,
                         SMEM_BYTES);
    hist_main<<<NCTA, 384, SMEM_BYTES>>>(x);
    hist_reduce<<<dim3(16, 24), 256>>>(out);
    hist_norm<<<384, 256>>>(out);
}

// round 12
// speedup vs baseline: 1.7402x; 1.0265x over previous
#include <cuda_runtime.h>
#include <cuda_fp16.h>
#include <cstdint>

#define H        64
#define NPIX     65536
#define LBATCH   8
#define NSPLIT   37                      // 8*37 = 296 CTAs = 148 SMs * 2 CTAs (1 wave)
#define NCTA     (LBATCH * NSPLIT)
#define NCHUNKS  512                     // 128-pixel chunks per image

// scratch: per-CTA 3 GEMM tiles: [cta][gemm][64*64]
__device__ float g_part[(size_t)NCTA * 3 * H * H];
// per-reduce-block partial totals: [lc][16 blocks]
__device__ float g_bsum[LBATCH * 3 * 16];

#define BUF_BYTES 0xC000u                      // 3*8*4*32 uint4 = 48 KB per buffer
#define SMEM_BYTES (2 * BUF_BYTES)             // 96 KB

__device__ __forceinline__ uint32_t smem_u32(const void* p) {
    uint32_t a;
    asm("{ .reg .u64 t; cvta.to.shared.u64 t, %1; cvt.u32.u64 %0, t; }" : "=r"(a) : "l"(p));
    return a;
}
__device__ __forceinline__ unsigned pk(float lo, float hi) {  // f32x2 -> f16x2
    unsigned r; asm("cvt.rn.f16x2.f32 %0, %2, %1;" : "=r"(r) : "f"(lo), "f"(hi));
    return r;
}
__device__ __forceinline__ unsigned hm2(unsigned a, unsigned b) {
    unsigned r; asm("mul.rn.f16x2 %0, %1, %2;" : "=r"(r) : "r"(a), "r"(b));
    return r;
}
__device__ __forceinline__ float lg2a(float x) {
    float r; asm("lg2.approx.f32 %0, %1;" : "=f"(r) : "f"(x));
    return r;
}
__device__ __forceinline__ float sqrta(float x) {
    float r; asm("sqrt.approx.f32 %0, %1;" : "=f"(r) : "f"(x));
    return r;
}
// two kernel values (pixels u0,u1 at same bin), sqrt-weight folded:
//   sw2 * 1/(1 + u^2), f16x2 (1 MUFU per 2 values). u stays f32 for precision.
__device__ __forceinline__ unsigned kv(float u0, float u1, unsigned sw2) {
    unsigned u = pk(u0, u1);
    unsigned t;
    asm("fma.rn.f16x2 %0, %1, %1, %2;" : "=r"(t) : "r"(u), "r"(0x3C003C00u));
    __half2 th = *(__half2*)&t;
    __half2 rh = h2rcp(th);
    return hm2(*(unsigned*)&rh, sw2);
}
__device__ __forceinline__ void mma16816(float* c, const unsigned* a, unsigned b0, unsigned b1) {
    asm volatile(
        "mma.sync.aligned.m16n8k16.row.col.f32.f16.f16.f32 "
        "{%0,%1,%2,%3}, {%4,%5,%6,%7}, {%8,%9}, {%0,%1,%2,%3};"
        : "+f"(c[0]), "+f"(c[1]), "+f"(c[2]), "+f"(c[3])
        : "r"(a[0]), "r"(a[1]), "r"(a[2]), "r"(a[3]), "r"(b0), "r"(b1));
}
__device__ __forceinline__ float shf(float v, int src) {
    return __shfl_sync(0xffffffffu, v, src);
}
__device__ __forceinline__ uint4 lds128(uint32_t a) {
    uint4 v;
    asm volatile("ld.shared.v4.b32 {%0,%1,%2,%3}, [%4];"
                 : "=r"(v.x), "=r"(v.y), "=r"(v.z), "=r"(v.w) : "r"(a));
    return v;
}
__device__ __forceinline__ void sts128(uint32_t a, uint4 v) {
    asm volatile("st.shared.v4.b32 [%0], {%1,%2,%3,%4};"
                 :: "r"(a), "r"(v.x), "r"(v.y), "r"(v.z), "r"(v.w) : "memory");
}

// 12 warps per CTA. Warp w: g = w%3 (vector/GEMM id), h = w/3 in 0..3.
// 128-px chunks, software-pipelined: region r = [interleaved consume(chunk r,
// buf r&1) + prep/produce(chunk r+1, buf (r&1)^1)], one barrier per region.
// Buffer layout (bytes, per buffer): ((vec*8+st)*4+m)*512 + L*16.
// All smem accesses are base-register + compile-time-immediate.
__global__ __launch_bounds__(384, 2) void hist_main(const float* __restrict__ x) {
    extern __shared__ uint4 img[];

    const int tid = threadIdx.x;
    const int w = tid >> 5;
    const int L = tid & 31;
    const int g = w % 3, h = w / 3;
    const int mi = h >> 1, ni = h & 1;
    const int bx = blockIdx.x;
    const int l = bx / NSPLIT, split = bx % NSPLIT;
    const int cbeg = (split * NCHUNKS) / NSPLIT;
    const int cend = ((split + 1) * NCHUNKS) / NSPLIT;
    const float* __restrict__ xp = x + (size_t)l * 3 * NPIX + 32 * h + L;

    const uint32_t sb = smem_u32(img);
    const int aimg = g >> 1;                  // A-operand image per GEMM
    const int bimg = (g == 0) ? 1 : 2;        // B-operand image per GEMM
    // consume bases (buf 0): A-frags at mtiles {2mi,2mi+1}, B at {2ni,2ni+1}
    uint32_t baseA = sb + (uint32_t)aimg * 16384 + (uint32_t)mi * 1024 + (uint32_t)L * 16;
    uint32_t baseB = sb + (uint32_t)bimg * 16384 + (uint32_t)ni * 1024 + (uint32_t)L * 16;
    // produce base (buf 0): vec g, steps 2h..2h+1
    uint32_t baseP = sb + (uint32_t)g * 16384 + (uint32_t)(2 * h) * 2048 + (uint32_t)L * 16;

    float acc[2][4][4];
#pragma unroll
    for (int m = 0; m < 2; m++)
#pragma unroll
        for (int j = 0; j < 4; j++)
#pragma unroll
            for (int k = 0; k < 4; k++) acc[m][j][k] = 0.0f;

    const float DLT = (6.0f / 63.0f) * 50.0f;             // scaled bin spacing
    const int q = L & 3;
    const float SC = 34.65735903f;            // ln(2)/sigma
    // hoisted bin-offset pairs per m-block: oo[2m]=o0(m), oo[2m+1]=o1(m)
    float oo[8];
#pragma unroll
    for (int m = 0; m < 8; m++)
        oo[m] = -150.0f + (float)((L >> 2) + 8 * m) * DLT;

    // prefetch first chunk (all 3 channels of this warp's 32 pixels)
    float pi0 = xp[(size_t)cbeg * 128];
    float pi1 = xp[(size_t)cbeg * 128 + NPIX];
    float pi2 = xp[(size_t)cbeg * 128 + 2 * NPIX];

    float pd[8];        // fragment-ordered d values, [si][4]
    unsigned ps[4];     // fragment-ordered packed sqrt-weights, [si][2]

    auto prep = [&](int ch) {
        float i0 = fminf(fmaxf(pi0, 0.0f), 1.0f);
        float i1 = fminf(fmaxf(pi1, 0.0f), 1.0f);
        float i2 = fminf(fmaxf(pi2, 0.0f), 1.0f);
        if (ch + 1 < cend) {
            pi0 = xp[(size_t)(ch + 1) * 128];
            pi1 = xp[(size_t)(ch + 1) * 128 + NPIX];
            pi2 = xp[(size_t)(ch + 1) * 128 + 2 * NPIX];
        }
        float l0 = lg2a(i0 + 1e-6f);
        float l1 = lg2a(i1 + 1e-6f);
        float l2 = lg2a(i2 + 1e-6f);
        float d = (g == 0) ? (l0 - l1) : (g == 1) ? (l0 - l2) : (l1 - l2);
        d *= SC;
        float s = fmaf(i0, i0, fmaf(i1, i1, fmaf(i2, i2, 1e-6f)));
        float sw = sqrta(sqrta(s));           // sqrt(Iy)
#pragma unroll
        for (int si = 0; si < 2; si++) {
            const int b0 = 16 * si + 2 * q;
            pd[4 * si + 0] = shf(d, b0);
            pd[4 * si + 1] = shf(d, b0 + 1);
            pd[4 * si + 2] = shf(d, b0 + 8);
            pd[4 * si + 3] = shf(d, b0 + 9);
            ps[2 * si + 0] = pk(shf(sw, b0),     shf(sw, b0 + 1));
            ps[2 * si + 1] = pk(shf(sw, b0 + 8), shf(sw, b0 + 9));
        }
    };

    const int nreg = cend - cbeg;
    // prologue: produce chunk cbeg into buf 0
    prep(cbeg);
#pragma unroll
    for (int k = 0; k < 8; k++) {
        const int si = k >> 2, m = k & 3;
        const float o0 = oo[2 * m], o1 = oo[2 * m + 1];
        uint4 v;
        v.x = kv(pd[4 * si + 0] - o0, pd[4 * si + 1] - o0, ps[2 * si]);
        v.y = kv(pd[4 * si + 0] - o1, pd[4 * si + 1] - o1, ps[2 * si]);
        v.z = kv(pd[4 * si + 2] - o0, pd[4 * si + 3] - o0, ps[2 * si + 1]);
        v.w = kv(pd[4 * si + 2] - o1, pd[4 * si + 3] - o1, ps[2 * si + 1]);
        sts128(baseP + (uint32_t)(si * 2048 + m * 512), v);
    }
    __syncthreads();

    int32_t pDelta = BUF_BYTES, cDelta = BUF_BYTES;
#pragma unroll 1
    for (int r = 0; r < nreg - 1; r++) {
        baseP += pDelta; pDelta = -pDelta;    // produce -> other buffer
        prep(cbeg + r + 1);
#pragma unroll
        for (int k = 0; k < 8; k++) {
            // consume K-step k from current buffer (immediate offsets)
            uint4 A0 = lds128(baseA + (uint32_t)(k * 2048));
            uint4 A1 = lds128(baseA + (uint32_t)(k * 2048 + 512));
            uint4 W0 = lds128(baseB + (uint32_t)(k * 2048));
            uint4 W1 = lds128(baseB + (uint32_t)(k * 2048 + 512));
            mma16816(acc[0][0], (const unsigned*)&A0, W0.x, W0.z);
            mma16816(acc[1][0], (const unsigned*)&A1, W0.x, W0.z);
            mma16816(acc[0][1], (const unsigned*)&A0, W0.y, W0.w);
            mma16816(acc[1][1], (const unsigned*)&A1, W0.y, W0.w);
            mma16816(acc[0][2], (const unsigned*)&A0, W1.x, W1.z);
            mma16816(acc[1][2], (const unsigned*)&A1, W1.x, W1.z);
            mma16816(acc[0][3], (const unsigned*)&A0, W1.y, W1.w);
            mma16816(acc[1][3], (const unsigned*)&A1, W1.y, W1.w);
            // produce block k of next chunk into the other buffer
            const int si = k >> 2, m = k & 3;
            const float o0 = oo[2 * m], o1 = oo[2 * m + 1];
            uint4 v;
            v.x = kv(pd[4 * si + 0] - o0, pd[4 * si + 1] - o0, ps[2 * si]);
            v.y = kv(pd[4 * si + 0] - o1, pd[4 * si + 1] - o1, ps[2 * si]);
            v.z = kv(pd[4 * si + 2] - o0, pd[4 * si + 3] - o0, ps[2 * si + 1]);
            v.w = kv(pd[4 * si + 2] - o1, pd[4 * si + 3] - o1, ps[2 * si + 1]);
            sts128(baseP + (uint32_t)(si * 2048 + m * 512), v);
        }
        __syncthreads();
        baseA += cDelta; baseB += cDelta; cDelta = -cDelta;
    }
    // final region: consume only
#pragma unroll
    for (int k = 0; k < 8; k++) {
        uint4 A0 = lds128(baseA + (uint32_t)(k * 2048));
        uint4 A1 = lds128(baseA + (uint32_t)(k * 2048 + 512));
        uint4 W0 = lds128(baseB + (uint32_t)(k * 2048));
        uint4 W1 = lds128(baseB + (uint32_t)(k * 2048 + 512));
        mma16816(acc[0][0], (const unsigned*)&A0, W0.x, W0.z);
        mma16816(acc[1][0], (const unsigned*)&A1, W0.x, W0.z);
        mma16816(acc[0][1], (const unsigned*)&A0, W0.y, W0.w);
        mma16816(acc[1][1], (const unsigned*)&A1, W0.y, W0.w);
        mma16816(acc[0][2], (const unsigned*)&A0, W1.x, W1.z);
        mma16816(acc[1][2], (const unsigned*)&A1, W1.x, W1.z);
        mma16816(acc[0][3], (const unsigned*)&A0, W1.y, W1.w);
        mma16816(acc[1][3], (const unsigned*)&A1, W1.y, W1.w);
    }

    // store this warp's 32x32 quadrant (non-atomic, private slot)
    float* dst = g_part + ((size_t)bx * 3 + g) * (H * H);
    const int r = L >> 2;
    const int qq = (L & 3) * 2;
#pragma unroll
    for (int m = 0; m < 2; m++)
#pragma unroll
        for (int jl = 0; jl < 4; jl++) {
            const int row0 = (2 * mi + m) * 16 + r;
            const int col = (4 * ni + jl) * 8 + qq;
            *(float2*)(dst + row0 * H + col)       = make_float2(acc[m][jl][0], acc[m][jl][1]);
            *(float2*)(dst + (row0 + 8) * H + col) = make_float2(acc[m][jl][2], acc[m][jl][3]);
        }
}

// grid (16, 24), 256 threads. Sums NSPLIT splits with the channel reversal
// mapping, writes out and a per-block partial total (no atomics, no zeroing).
__global__ void hist_reduce(float* __restrict__ out) {
    const int lc = blockIdx.y;
    const int c = lc % 3, lidx = lc / 3;
    const int e = blockIdx.x * 256 + threadIdx.x;  // 0..4095
    const int u = e >> 6, v = e & 63;
    int se;
    if (c == 0)      se = e;                        // identity
    else if (c == 1) se = ((63 - u) << 6) | v;      // row reversal
    else             se = 4095 - e;                 // row+col reversal
    const float* __restrict__ src =
        g_part + ((size_t)(lidx * NSPLIT) * 3 + c) * (H * H) + se;
    float a0 = 0, a1 = 0, a2 = 0, a3 = 0, a4 = 0, a5 = 0, a6 = 0, a7 = 0;
    int sp = 0;
#pragma unroll 1
    for (; sp + 8 <= NSPLIT; sp += 8) {
        a0 += src[(size_t)(sp + 0) * 3 * (H * H)];
        a1 += src[(size_t)(sp + 1) * 3 * (H * H)];
        a2 += src[(size_t)(sp + 2) * 3 * (H * H)];
        a3 += src[(size_t)(sp + 3) * 3 * (H * H)];
        a4 += src[(size_t)(sp + 4) * 3 * (H * H)];
        a5 += src[(size_t)(sp + 5) * 3 * (H * H)];
        a6 += src[(size_t)(sp + 6) * 3 * (H * H)];
        a7 += src[(size_t)(sp + 7) * 3 * (H * H)];
    }
    for (; sp < NSPLIT; sp++) a0 += src[(size_t)sp * 3 * (H * H)];
    float s = ((a0 + a1) + (a2 + a3)) + ((a4 + a5) + (a6 + a7));
    out[lc * (H * H) + e] = s;

    __shared__ float red[256];
    red[threadIdx.x] = s;
    __syncthreads();
#pragma unroll
    for (int st = 128; st > 0; st >>= 1) {
        if (threadIdx.x < st) red[threadIdx.x] += red[threadIdx.x + st];
        __syncthreads();
    }
    if (threadIdx.x == 0)
        g_bsum[lc * 16 + blockIdx.x] = red[0];
}

// grid 384, 256 threads. Each block covers 256 contiguous outputs (same l).
__global__ void hist_norm(float* __restrict__ out) {
    __shared__ float red[48];
    const int l = blockIdx.x / 48;                  // 12288 per l / 256 = 48 blocks
    if (threadIdx.x < 48) red[threadIdx.x] = g_bsum[l * 48 + threadIdx.x];
    __syncthreads();
    float tot = 1e-6f;
#pragma unroll
    for (int k = 0; k < 48; k++) tot += red[k];
    const int idx = blockIdx.x * 256 + threadIdx.x;
    out[idx] = out[idx] / tot;
}

extern "C" void kernel_launch(void* const* d_in, const int* in_sizes, int n_in,
                              void* d_out, int out_size) {
    const float* x = (const float*)d_in[0];
    float* out = (float*)d_out;
    (void)in_sizes; (void)n_in; (void)out_size;

    cudaFuncSetAttribute(hist_main, cudaFuncAttributeMaxDynamicSharedMemorySize,
                         SMEM_BYTES);
    hist_main<<<NCTA, 384, SMEM_BYTES>>>(x);
    hist_reduce<<<dim3(16, 24), 256>>>(out);
    hist_norm<<<384, 256>>>(out);
}

// round 13
// speedup vs baseline: 1.7867x; 1.0267x over previous
#include <cuda_runtime.h>
#include <cuda_fp16.h>
#include <cstdint>

#define H        64
#define NPIX     65536
#define LBATCH   8
#define NSPLIT   37                      // 8*37 = 296 CTAs = 148 SMs * 2 CTAs (1 wave)
#define NCTA     (LBATCH * NSPLIT)
#define NCHUNKS  512                     // 128-pixel chunks per image

// scratch: per-CTA 3 GEMM tiles: [cta][gemm][64*64]
__device__ float g_part[(size_t)NCTA * 3 * H * H];
// per-reduce-block partial totals: [lc][16 blocks]
__device__ float g_bsum[LBATCH * 3 * 16];

#define BUF_BYTES 0xC000u                      // 3*8*4*32 uint4 = 48 KB per buffer
#define SMEM_BYTES (2 * BUF_BYTES)             // 96 KB

__device__ __forceinline__ uint32_t smem_u32(const void* p) {
    uint32_t a;
    asm("{ .reg .u64 t; cvta.to.shared.u64 t, %1; cvt.u32.u64 %0, t; }" : "=r"(a) : "l"(p));
    return a;
}
__device__ __forceinline__ unsigned pk(float lo, float hi) {  // f32x2 -> f16x2
    unsigned r; asm("cvt.rn.f16x2.f32 %0, %2, %1;" : "=r"(r) : "f"(lo), "f"(hi));
    return r;
}
__device__ __forceinline__ unsigned hm2(unsigned a, unsigned b) {
    unsigned r; asm("mul.rn.f16x2 %0, %1, %2;" : "=r"(r) : "r"(a), "r"(b));
    return r;
}
__device__ __forceinline__ float lg2a(float x) {
    float r; asm("lg2.approx.f32 %0, %1;" : "=f"(r) : "f"(x));
    return r;
}
__device__ __forceinline__ float sqrta(float x) {
    float r; asm("sqrt.approx.f32 %0, %1;" : "=f"(r) : "f"(x));
    return r;
}
__device__ __forceinline__ float rcpa(float x) {
    float r; asm("rcp.approx.ftz.f32 %0, %1;" : "=f"(r) : "f"(x));
    return r;
}
// two kernel values (pixels u0,u1 at same bin), sqrt-weight folded, via the
// product-reciprocal trick: ONE f32 MUFU per pair, f32 math until final pack.
//   a=1+u0^2, b=1+u1^2, r=rcp(a*b) -> K0=b*r=1/a, K1=a*r=1/b
__device__ __forceinline__ unsigned kv(float u0, float u1, unsigned sw2) {
    float a = fmaf(u0, u0, 1.0f);
    float b = fmaf(u1, u1, 1.0f);
    float r = rcpa(a * b);
    return hm2(pk(b * r, a * r), sw2);
}
__device__ __forceinline__ void mma16816(float* c, const unsigned* a, unsigned b0, unsigned b1) {
    asm volatile(
        "mma.sync.aligned.m16n8k16.row.col.f32.f16.f16.f32 "
        "{%0,%1,%2,%3}, {%4,%5,%6,%7}, {%8,%9}, {%0,%1,%2,%3};"
        : "+f"(c[0]), "+f"(c[1]), "+f"(c[2]), "+f"(c[3])
        : "r"(a[0]), "r"(a[1]), "r"(a[2]), "r"(a[3]), "r"(b0), "r"(b1));
}
__device__ __forceinline__ float shf(float v, int src) {
    return __shfl_sync(0xffffffffu, v, src);
}
__device__ __forceinline__ uint4 lds128(uint32_t a) {
    uint4 v;
    asm volatile("ld.shared.v4.b32 {%0,%1,%2,%3}, [%4];"
                 : "=r"(v.x), "=r"(v.y), "=r"(v.z), "=r"(v.w) : "r"(a));
    return v;
}
__device__ __forceinline__ void sts128(uint32_t a, uint4 v) {
    asm volatile("st.shared.v4.b32 [%0], {%1,%2,%3,%4};"
                 :: "r"(a), "r"(v.x), "r"(v.y), "r"(v.z), "r"(v.w) : "memory");
}

// 12 warps per CTA. Warp w: g = w%3 (vector/GEMM id), h = w/3 in 0..3.
// 128-px chunks, software-pipelined: region r = [interleaved consume(chunk r,
// buf r&1) + prep/produce(chunk r+1, buf (r&1)^1)], one barrier per region.
// Buffer layout (bytes, per buffer): ((vec*8+st)*4+m)*512 + L*16.
__global__ __launch_bounds__(384, 2) void hist_main(const float* __restrict__ x) {
    extern __shared__ uint4 img[];

    const int tid = threadIdx.x;
    const int w = tid >> 5;
    const int L = tid & 31;
    const int g = w % 3, h = w / 3;
    const int mi = h >> 1, ni = h & 1;
    const int bx = blockIdx.x;
    const int l = bx / NSPLIT, split = bx % NSPLIT;
    const int cbeg = (split * NCHUNKS) / NSPLIT;
    const int cend = ((split + 1) * NCHUNKS) / NSPLIT;
    const float* __restrict__ xp = x + (size_t)l * 3 * NPIX + 32 * h + L;

    const uint32_t sb = smem_u32(img);
    const int aimg = g >> 1;                  // A-operand image per GEMM
    const int bimg = (g == 0) ? 1 : 2;        // B-operand image per GEMM
    uint32_t baseA = sb + (uint32_t)aimg * 16384 + (uint32_t)mi * 1024 + (uint32_t)L * 16;
    uint32_t baseB = sb + (uint32_t)bimg * 16384 + (uint32_t)ni * 1024 + (uint32_t)L * 16;
    uint32_t baseP = sb + (uint32_t)g * 16384 + (uint32_t)(2 * h) * 2048 + (uint32_t)L * 16;

    float acc[2][4][4];
#pragma unroll
    for (int m = 0; m < 2; m++)
#pragma unroll
        for (int j = 0; j < 4; j++)
#pragma unroll
            for (int k = 0; k < 4; k++) acc[m][j][k] = 0.0f;

    const float DLT = (6.0f / 63.0f) * 50.0f;             // scaled bin spacing
    const int q = L & 3;
    const float SC = 34.65735903f;            // ln(2)/sigma
    // hoisted bin-offset pairs per m-block: oo[2m]=o0(m), oo[2m+1]=o1(m)
    float oo[8];
#pragma unroll
    for (int m = 0; m < 8; m++)
        oo[m] = -150.0f + (float)((L >> 2) + 8 * m) * DLT;

    // prefetch first chunk (all 3 channels of this warp's 32 pixels)
    float pi0 = xp[(size_t)cbeg * 128];
    float pi1 = xp[(size_t)cbeg * 128 + NPIX];
    float pi2 = xp[(size_t)cbeg * 128 + 2 * NPIX];

    float pd[8];        // fragment-ordered d values, [si][4]
    unsigned ps[4];     // fragment-ordered packed sqrt-weights, [si][2]

    auto prep = [&](int ch) {
        float i0 = fminf(fmaxf(pi0, 0.0f), 1.0f);
        float i1 = fminf(fmaxf(pi1, 0.0f), 1.0f);
        float i2 = fminf(fmaxf(pi2, 0.0f), 1.0f);
        if (ch + 1 < cend) {
            pi0 = xp[(size_t)(ch + 1) * 128];
            pi1 = xp[(size_t)(ch + 1) * 128 + NPIX];
            pi2 = xp[(size_t)(ch + 1) * 128 + 2 * NPIX];
        }
        float l0 = lg2a(i0 + 1e-6f);
        float l1 = lg2a(i1 + 1e-6f);
        float l2 = lg2a(i2 + 1e-6f);
        float d = (g == 0) ? (l0 - l1) : (g == 1) ? (l0 - l2) : (l1 - l2);
        d *= SC;
        float s = fmaf(i0, i0, fmaf(i1, i1, fmaf(i2, i2, 1e-6f)));
        float sw = sqrta(sqrta(s));           // sqrt(Iy)
#pragma unroll
        for (int si = 0; si < 2; si++) {
            const int b0 = 16 * si + 2 * q;
            pd[4 * si + 0] = shf(d, b0);
            pd[4 * si + 1] = shf(d, b0 + 1);
            pd[4 * si + 2] = shf(d, b0 + 8);
            pd[4 * si + 3] = shf(d, b0 + 9);
            ps[2 * si + 0] = pk(shf(sw, b0),     shf(sw, b0 + 1));
            ps[2 * si + 1] = pk(shf(sw, b0 + 8), shf(sw, b0 + 9));
        }
    };

    const int nreg = cend - cbeg;
    // prologue: produce chunk cbeg into buf 0
    prep(cbeg);
#pragma unroll
    for (int k = 0; k < 8; k++) {
        const int si = k >> 2, m = k & 3;
        const float o0 = oo[2 * m], o1 = oo[2 * m + 1];
        uint4 v;
        v.x = kv(pd[4 * si + 0] - o0, pd[4 * si + 1] - o0, ps[2 * si]);
        v.y = kv(pd[4 * si + 0] - o1, pd[4 * si + 1] - o1, ps[2 * si]);
        v.z = kv(pd[4 * si + 2] - o0, pd[4 * si + 3] - o0, ps[2 * si + 1]);
        v.w = kv(pd[4 * si + 2] - o1, pd[4 * si + 3] - o1, ps[2 * si + 1]);
        sts128(baseP + (uint32_t)(si * 2048 + m * 512), v);
    }
    __syncthreads();

    int32_t pDelta = BUF_BYTES, cDelta = BUF_BYTES;
#pragma unroll 1
    for (int r = 0; r < nreg - 1; r++) {
        baseP += pDelta; pDelta = -pDelta;    // produce -> other buffer
        prep(cbeg + r + 1);
#pragma unroll
        for (int k = 0; k < 8; k++) {
            // consume K-step k from current buffer (immediate offsets)
            uint4 A0 = lds128(baseA + (uint32_t)(k * 2048));
            uint4 A1 = lds128(baseA + (uint32_t)(k * 2048 + 512));
            uint4 W0 = lds128(baseB + (uint32_t)(k * 2048));
            uint4 W1 = lds128(baseB + (uint32_t)(k * 2048 + 512));
            mma16816(acc[0][0], (const unsigned*)&A0, W0.x, W0.z);
            mma16816(acc[1][0], (const unsigned*)&A1, W0.x, W0.z);
            mma16816(acc[0][1], (const unsigned*)&A0, W0.y, W0.w);
            mma16816(acc[1][1], (const unsigned*)&A1, W0.y, W0.w);
            mma16816(acc[0][2], (const unsigned*)&A0, W1.x, W1.z);
            mma16816(acc[1][2], (const unsigned*)&A1, W1.x, W1.z);
            mma16816(acc[0][3], (const unsigned*)&A0, W1.y, W1.w);
            mma16816(acc[1][3], (const unsigned*)&A1, W1.y, W1.w);
            // produce block k of next chunk into the other buffer
            const int si = k >> 2, m = k & 3;
            const float o0 = oo[2 * m], o1 = oo[2 * m + 1];
            uint4 v;
            v.x = kv(pd[4 * si + 0] - o0, pd[4 * si + 1] - o0, ps[2 * si]);
            v.y = kv(pd[4 * si + 0] - o1, pd[4 * si + 1] - o1, ps[2 * si]);
            v.z = kv(pd[4 * si + 2] - o0, pd[4 * si + 3] - o0, ps[2 * si + 1]);
            v.w = kv(pd[4 * si + 2] - o1, pd[4 * si + 3] - o1, ps[2 * si + 1]);
            sts128(baseP + (uint32_t)(si * 2048 + m * 512), v);
        }
        __syncthreads();
        baseA += cDelta; baseB += cDelta; cDelta = -cDelta;
    }
    // final region: consume only
#pragma unroll
    for (int k = 0; k < 8; k++) {
        uint4 A0 = lds128(baseA + (uint32_t)(k * 2048));
        uint4 A1 = lds128(baseA + (uint32_t)(k * 2048 + 512));
        uint4 W0 = lds128(baseB + (uint32_t)(k * 2048));
        uint4 W1 = lds128(baseB + (uint32_t)(k * 2048 + 512));
        mma16816(acc[0][0], (const unsigned*)&A0, W0.x, W0.z);
        mma16816(acc[1][0], (const unsigned*)&A1, W0.x, W0.z);
        mma16816(acc[0][1], (const unsigned*)&A0, W0.y, W0.w);
        mma16816(acc[1][1], (const unsigned*)&A1, W0.y, W0.w);
        mma16816(acc[0][2], (const unsigned*)&A0, W1.x, W1.z);
        mma16816(acc[1][2], (const unsigned*)&A1, W1.x, W1.z);
        mma16816(acc[0][3], (const unsigned*)&A0, W1.y, W1.w);
        mma16816(acc[1][3], (const unsigned*)&A1, W1.y, W1.w);
    }

    // store this warp's 32x32 quadrant (non-atomic, private slot)
    float* dst = g_part + ((size_t)bx * 3 + g) * (H * H);
    const int r = L >> 2;
    const int qq = (L & 3) * 2;
#pragma unroll
    for (int m = 0; m < 2; m++)
#pragma unroll
        for (int jl = 0; jl < 4; jl++) {
            const int row0 = (2 * mi + m) * 16 + r;
            const int col = (4 * ni + jl) * 8 + qq;
            *(float2*)(dst + row0 * H + col)       = make_float2(acc[m][jl][0], acc[m][jl][1]);
            *(float2*)(dst + (row0 + 8) * H + col) = make_float2(acc[m][jl][2], acc[m][jl][3]);
        }
}

// grid (16, 24), 256 threads. Sums NSPLIT splits with the channel reversal
// mapping, writes out and a per-block partial total (no atomics, no zeroing).
__global__ void hist_reduce(float* __restrict__ out) {
    const int lc = blockIdx.y;
    const int c = lc % 3, lidx = lc / 3;
    const int e = blockIdx.x * 256 + threadIdx.x;  // 0..4095
    const int u = e >> 6, v = e & 63;
    int se;
    if (c == 0)      se = e;                        // identity
    else if (c == 1) se = ((63 - u) << 6) | v;      // row reversal
    else             se = 4095 - e;                 // row+col reversal
    const float* __restrict__ src =
        g_part + ((size_t)(lidx * NSPLIT) * 3 + c) * (H * H) + se;
    float a0 = 0, a1 = 0, a2 = 0, a3 = 0, a4 = 0, a5 = 0, a6 = 0, a7 = 0;
    int sp = 0;
#pragma unroll 1
    for (; sp + 8 <= NSPLIT; sp += 8) {
        a0 += src[(size_t)(sp + 0) * 3 * (H * H)];
        a1 += src[(size_t)(sp + 1) * 3 * (H * H)];
        a2 += src[(size_t)(sp + 2) * 3 * (H * H)];
        a3 += src[(size_t)(sp + 3) * 3 * (H * H)];
        a4 += src[(size_t)(sp + 4) * 3 * (H * H)];
        a5 += src[(size_t)(sp + 5) * 3 * (H * H)];
        a6 += src[(size_t)(sp + 6) * 3 * (H * H)];
        a7 += src[(size_t)(sp + 7) * 3 * (H * H)];
    }
    for (; sp < NSPLIT; sp++) a0 += src[(size_t)sp * 3 * (H * H)];
    float s = ((a0 + a1) + (a2 + a3)) + ((a4 + a5) + (a6 + a7));
    out[lc * (H * H) + e] = s;

    __shared__ float red[256];
    red[threadIdx.x] = s;
    __syncthreads();
#pragma unroll
    for (int st = 128; st > 0; st >>= 1) {
        if (threadIdx.x < st) red[threadIdx.x] += red[threadIdx.x + st];
        __syncthreads();
    }
    if (threadIdx.x == 0)
        g_bsum[lc * 16 + blockIdx.x] = red[0];
}

// grid 384, 256 threads. Each block covers 256 contiguous outputs (same l).
__global__ void hist_norm(float* __restrict__ out) {
    __shared__ float red[48];
    const int l = blockIdx.x / 48;                  // 12288 per l / 256 = 48 blocks
    if (threadIdx.x < 48) red[threadIdx.x] = g_bsum[l * 48 + threadIdx.x];
    __syncthreads();
    float tot = 1e-6f;
#pragma unroll
    for (int k = 0; k < 48; k++) tot += red[k];
    const int idx = blockIdx.x * 256 + threadIdx.x;
    out[idx] = out[idx] / tot;
}

extern "C" void kernel_launch(void* const* d_in, const int* in_sizes, int n_in,
                              void* d_out, int out_size) {
    const float* x = (const float*)d_in[0];
    float* out = (float*)d_out;
    (void)in_sizes; (void)n_in; (void)out_size;

    cudaFuncSetAttribute(hist_main, cudaFuncAttributeMaxDynamicSharedMemorySize,
                         SMEM_BYTES);
    hist_main<<<NCTA, 384, SMEM_BYTES>>>(x);
    hist_reduce<<<dim3(16, 24), 256>>>(out);
    hist_norm<<<384, 256>>>(out);
}